// round 11
// baseline (speedup 1.0000x reference)
#include <cuda_runtime.h>
#include <cstdint>

// ---------------- problem constants ----------------
#define BB   2
#define SS   2048
#define DD   2048
#define NHN  16
#define HD   128
#define NHD  2048              // NHN*HD
#define MM   (BB*SS)           // 4096 rows for prefill GEMMs
#define ATT_SCALE 0.08838834764831845f   // 1/sqrt(128)
#define PREFILL_ELEMS (BB*SS*DD)         // 8388608

// perm within each 8-block of k: k -> (k&~7) | ((k&3)<<1) | ((k>>2)&1)
// pairs original (k, k+4) at adjacent addresses.
// inverse (within 32-block): p -> (p&24) | ((p&1)<<2) | ((p>>1)&3)
#define INV32(p) (((p) & 24) | (((p) & 1) << 2) | (((p) >> 1) & 3))
#define PERM8(k) (((k) & ~7) | (((k) & 3) << 1) | (((k) >> 2) & 1))

// ---------------- scratch (device globals; no allocation allowed) ----------------
__device__ float g_q[(size_t)BB*NHN*SS*HD];   // [B,N,S,H] (tf32-rounded)
__device__ float g_k[(size_t)BB*NHN*SS*HD];
__device__ float g_v[(size_t)BB*NHN*SS*HD];
__device__ float g_attn[(size_t)BB*SS*NHD];   // [B,S,N*H] tf32, k-permuted per 8-block
__device__ float g_q1[BB*NHD];
__device__ float g_k1[BB*NHD];
__device__ float g_v1[BB*NHD];
__device__ float g_attn1[BB*NHD];
// decode split-K partials
__device__ float g_dm[32*8];
__device__ float g_dl[32*8];
__device__ float g_do[32*8*HD];
// tf32-pre-rounded inputs (g_xt, g_wot additionally k-permuted)
__device__ float g_xt[(size_t)MM*DD];
__device__ float g_wqt[(size_t)DD*NHD];
__device__ float g_wkt[(size_t)DD*NHD];
__device__ float g_wvt[(size_t)DD*NHD];
__device__ float g_wot[(size_t)DD*NHD];

// =====================================================================
// tf32 / cp.async helpers
// =====================================================================
__device__ __forceinline__ uint32_t f2tf(float f) {
    uint32_t u;
    asm("cvt.rna.tf32.f32 %0, %1;" : "=r"(u) : "f"(f));
    return u;
}

__device__ __forceinline__ void mma_tf32(float* c, const uint32_t* a, const uint32_t* b) {
    asm volatile(
        "mma.sync.aligned.m16n8k8.row.col.f32.tf32.tf32.f32 "
        "{%0,%1,%2,%3}, {%4,%5,%6,%7}, {%8,%9}, {%0,%1,%2,%3};"
        : "+f"(c[0]), "+f"(c[1]), "+f"(c[2]), "+f"(c[3])
        : "r"(a[0]), "r"(a[1]), "r"(a[2]), "r"(a[3]), "r"(b[0]), "r"(b[1]));
}

__device__ __forceinline__ void cp16(uint32_t dst_smem, const void* src) {
    asm volatile("cp.async.cg.shared.global [%0], [%1], 16;"
                 :: "r"(dst_smem), "l"(src));
}
#define CP_COMMIT() asm volatile("cp.async.commit_group;" ::: "memory")
#define CP_WAIT(N)  asm volatile("cp.async.wait_group %0;" :: "n"(N) : "memory")

// =====================================================================
// pre-round to tf32; segs 0 (x) and 4 (wo) additionally k-permuted.
// =====================================================================
__global__ void preround(const float* __restrict__ x,  const float* __restrict__ wq,
                         const float* __restrict__ wk, const float* __restrict__ wv,
                         const float* __restrict__ wo) {
    int t = blockIdx.x * 256 + threadIdx.x;
    int seg = blockIdx.y;
    const float* s; float* d; int n4; bool prm;
    if (seg == 0)      { s = x;  d = g_xt;  n4 = (MM*DD) / 4; prm = true;  }
    else if (seg == 1) { s = wq; d = g_wqt; n4 = (DD*NHD) / 4; prm = false; }
    else if (seg == 2) { s = wk; d = g_wkt; n4 = (DD*NHD) / 4; prm = false; }
    else if (seg == 3) { s = wv; d = g_wvt; n4 = (DD*NHD) / 4; prm = false; }
    else               { s = wo; d = g_wot; n4 = (DD*NHD) / 4; prm = true;  }
    if (t >= n4) return;
    if (!prm) {
        float4 v = ((const float4*)s)[t];
        ((uint4*)d)[t] = make_uint4(f2tf(v.x), f2tf(v.y), f2tf(v.z), f2tf(v.w));
    } else {
        int e0 = t * 4;
        uint32_t o[4];
        #pragma unroll
        for (int u = 0; u < 4; u++) {
            int e = e0 + u, c = e & 31;
            o[u] = f2tf(s[(e & ~31) + INV32(c)]);
        }
        ((uint4*)d)[t] = make_uint4(o[0], o[1], o[2], o[3]);
    }
}

// =====================================================================
// tf32 tensor-core GEMM. CTA 128x128x32, warp tile 64x32 (2Mx4N),
// 3-stage cp.async. Contraction dim k-permuted -> A fragments via LDS.64.
// NT=0 (QKV fused by z): A=g_xt(perm), B=W [k][n] row-remapped at load;
//                        scatter to g_q/g_k/g_v (normal layout).
// NT=1 (out-proj): A=g_attn(perm), B=g_wot [n][k](perm); C -> out fp32.
// =====================================================================
#define STAGES 3
#define AS_W   (128*36)
#define BNN_W  (32*136)
#define BNT_W  (128*36)
#define GEMM_SMEM_NN ((STAGES*(AS_W + BNN_W))*4)   // 107520
#define GEMM_SMEM_NT ((STAGES*(AS_W + BNT_W))*4)   // 110592

template<int NT>
__global__ __launch_bounds__(256) void mma_gemm(float* __restrict__ out) {
    extern __shared__ uint32_t smw[];
    constexpr int BW = NT ? BNT_W : BNN_W;
    uint32_t* Asm = smw;
    uint32_t* Bsm = smw + STAGES * AS_W;
    const uint32_t sa_base = (uint32_t)__cvta_generic_to_shared(smw);
    const uint32_t sb_base = sa_base + STAGES * AS_W * 4;

    const int z = blockIdx.z;
    const float* A    = NT ? g_attn : g_xt;
    const float* Bsrc = NT ? g_wot
                      : (z == 0) ? g_wqt : (z == 1) ? g_wkt : g_wvt;

    const int tid = threadIdx.x;
    const int m0 = blockIdx.y * 128, n0 = blockIdx.x * 128;
    const int warp = tid >> 5, lane = tid & 31;
    const int wm = warp >> 2, wn = warp & 3;   // 2(M) x 4(N), warp tile 64x32
    const int g  = lane >> 2, c4 = lane & 3;

    float acc[4][4][4];
    #pragma unroll
    for (int i = 0; i < 4; i++)
        #pragma unroll
        for (int j = 0; j < 4; j++)
            #pragma unroll
            for (int e = 0; e < 4; e++) acc[i][j][e] = 0.f;

    auto load_stage = [&](int st, int kt) {
        uint32_t ab = sa_base + st * AS_W * 4;
        const float* asrc = A + (size_t)m0 * DD + (size_t)kt * 32;
        #pragma unroll
        for (int i = 0; i < 4; i++) {
            int id = tid + i * 256;
            int row = id >> 3, co = (id & 7) << 2;
            cp16(ab + (row * 36 + co) * 4, asrc + (size_t)row * DD + co);
        }
        uint32_t bb = sb_base + st * BW * 4;
        if (!NT) {
            // smem row kr holds gmem row kt*32 + INV32(kr)
            const float* bs = Bsrc + (size_t)kt * 32 * NHD + n0;
            #pragma unroll
            for (int i = 0; i < 4; i++) {
                int id = tid + i * 256;
                int kr = id >> 5, co = (id & 31) << 2;
                int src = INV32(kr);
                cp16(bb + (kr * 136 + co) * 4, bs + (size_t)src * NHD + co);
            }
        } else {
            const float* bs = Bsrc + (size_t)n0 * NHD + (size_t)kt * 32;
            #pragma unroll
            for (int i = 0; i < 4; i++) {
                int id = tid + i * 256;
                int nr = id >> 3, co = (id & 7) << 2;
                cp16(bb + (nr * 36 + co) * 4, bs + (size_t)nr * NHD + co);
            }
        }
        CP_COMMIT();
    };

    auto compute = [&](int st) {
        const uint32_t* Ab = Asm + st * AS_W + (wm * 64) * 36;
        const uint32_t* Bb = Bsm + st * BW;
        #pragma unroll
        for (int kk = 0; kk < 4; kk++) {
            const int pc = kk * 8 + c4 * 2;   // permuted position of (kk*8+c4, +4)
            uint32_t af[4][4];
            #pragma unroll
            for (int i = 0; i < 4; i++) {
                int r = i * 16 + g;
                uint2 u0 = *(const uint2*)&Ab[r * 36 + pc];
                uint2 u1 = *(const uint2*)&Ab[(r + 8) * 36 + pc];
                af[i][0] = u0.x; af[i][1] = u1.x; af[i][2] = u0.y; af[i][3] = u1.y;
            }
            #pragma unroll
            for (int j = 0; j < 4; j++) {
                uint32_t bf[2];
                if (!NT) {
                    bf[0] = Bb[pc * 136 + wn * 32 + j * 8 + g];
                    bf[1] = Bb[(pc + 1) * 136 + wn * 32 + j * 8 + g];
                } else {
                    uint2 ub = *(const uint2*)&Bb[(wn * 32 + j * 8 + g) * 36 + pc];
                    bf[0] = ub.x; bf[1] = ub.y;
                }
                #pragma unroll
                for (int i = 0; i < 4; i++)
                    mma_tf32(acc[i][j], af[i], bf);
            }
        }
    };

    load_stage(0, 0);
    load_stage(1, 1);
    for (int kt = 0; kt < 64; kt++) {
        if (kt < 62) CP_WAIT(1); else CP_WAIT(0);
        __syncthreads();
        if (kt + 2 < 64) load_stage((kt + 2) % STAGES, kt + 2);
        compute(kt % STAGES);
    }

    if (!NT) {
        const int head = blockIdx.x;   // BN=128 == HD
        float* dst = (z == 0) ? g_q : (z == 1) ? g_k : g_v;
        #pragma unroll
        for (int i = 0; i < 4; i++) {
            int m = m0 + wm * 64 + i * 16 + g;
            int b = m >> 11, s = m & 2047;
            #pragma unroll
            for (int j = 0; j < 4; j++) {
                int h = wn * 32 + j * 8 + 2 * c4;
                size_t o = ((size_t)(b * NHN + head) * SS + s) * HD + h;
                *(float2*)&dst[o] = make_float2(__uint_as_float(f2tf(acc[i][j][0])),
                                                __uint_as_float(f2tf(acc[i][j][1])));
                *(float2*)&dst[o + 8 * HD] = make_float2(__uint_as_float(f2tf(acc[i][j][2])),
                                                         __uint_as_float(f2tf(acc[i][j][3])));
            }
        }
    } else {
        #pragma unroll
        for (int i = 0; i < 4; i++) {
            int m = m0 + wm * 64 + i * 16 + g;
            #pragma unroll
            for (int j = 0; j < 4; j++) {
                int col = n0 + wn * 32 + j * 8 + 2 * c4;
                *(float2*)&out[(size_t)m * DD + col] =
                    make_float2(acc[i][j][0], acc[i][j][1]);
                *(float2*)&out[(size_t)(m + 8) * DD + col] =
                    make_float2(acc[i][j][2], acc[i][j][3]);
            }
        }
    }
}

// =====================================================================
// tf32 tensor-core flash attention (prefill, causal).
// K prefetch + double-buffered V.  P stored key-permuted + V smem rows
// key-permuted -> P fragments via LDS.64 (smem-internal only).
// Epilogue writes g_attn k-permuted per 8-block (consumed by NT GEMM).
// =====================================================================
#define FA_BM 128
#define FA_BN 64
#define QS_STRIDE 132
#define KS_STRIDE 132
#define VS_STRIDE 136
#define PS_STRIDE 68
#define QS_SIZE (FA_BM*QS_STRIDE)
#define KS_SIZE (FA_BN*KS_STRIDE)
#define VS_W    (FA_BN*VS_STRIDE)
#define PS_SIZE (FA_BM*PS_STRIDE)
#define FA_SMEM_BYTES ((QS_SIZE+KS_SIZE+2*VS_W+PS_SIZE)*4)   // 205824

__global__ __launch_bounds__(256, 1) void flash_attn_tc() {
    extern __shared__ uint32_t smu[];
    uint32_t* Qs = smu;
    uint32_t* Ks = smu + QS_SIZE;
    uint32_t* Vs = Ks + KS_SIZE;            // two buffers of VS_W
    uint32_t* Ps = Vs + 2 * VS_W;
    const uint32_t s_q = (uint32_t)__cvta_generic_to_shared(smu);
    const uint32_t s_k = s_q + QS_SIZE * 4;
    const uint32_t s_v = s_k + KS_SIZE * 4;

    const int qt  = blockIdx.x;
    const int bn  = blockIdx.y;
    const int tid = threadIdx.x;
    const int warp = tid >> 5, lane = tid & 31;
    const int g = lane >> 2, c4 = lane & 3;

    const float* qh = g_q + (size_t)bn * SS * HD;
    const float* kh = g_k + (size_t)bn * SS * HD;
    const float* vh = g_v + (size_t)bn * SS * HD;

    {
        const float* src = qh + (size_t)qt * FA_BM * HD;
        #pragma unroll
        for (int i = 0; i < 16; i++) {
            int id = tid + i * 256;
            int r = id >> 5, c = (id & 31) << 2;
            cp16(s_q + (r * QS_STRIDE + c) * 4, src + (size_t)r * HD + c);
        }
        CP_COMMIT();
    }
    {
        #pragma unroll
        for (int i = 0; i < 8; i++) {
            int id = tid + i * 256;
            int r = id >> 5, c = (id & 31) << 2;
            cp16(s_k + (r * KS_STRIDE + c) * 4, kh + (size_t)r * HD + c);
            cp16(s_v + (PERM8(r) * VS_STRIDE + c) * 4, vh + (size_t)r * HD + c);
        }
        CP_COMMIT();
    }

    float m_i[2] = {-INFINITY, -INFINITY};
    float l_i[2] = {0.f, 0.f};
    float oacc[16][4];
    #pragma unroll
    for (int nt = 0; nt < 16; nt++)
        #pragma unroll
        for (int e = 0; e < 4; e++) oacc[nt][e] = 0.f;

    const int nkt = 2 * qt + 2;
    const uint32_t* Qw = Qs + (warp * 16) * QS_STRIDE;
    const uint32_t* Pw = Ps + (warp * 16) * PS_STRIDE;
    int buf = 0;

    for (int kt = 0; kt < nkt; kt++) {
        CP_WAIT(0);
        __syncthreads();

        float sacc[8][4];
        #pragma unroll
        for (int nt = 0; nt < 8; nt++)
            #pragma unroll
            for (int e = 0; e < 4; e++) sacc[nt][e] = 0.f;

        #pragma unroll
        for (int kk = 0; kk < 16; kk++) {
            const int cb = kk * 8 + c4;
            uint32_t af[4];
            af[0] = Qw[g * QS_STRIDE + cb];
            af[1] = Qw[(g + 8) * QS_STRIDE + cb];
            af[2] = Qw[g * QS_STRIDE + cb + 4];
            af[3] = Qw[(g + 8) * QS_STRIDE + cb + 4];
            #pragma unroll
            for (int nt = 0; nt < 8; nt++) {
                uint32_t bf[2];
                bf[0] = Ks[(nt * 8 + g) * KS_STRIDE + cb];
                bf[1] = Ks[(nt * 8 + g) * KS_STRIDE + cb + 4];
                mma_tf32(sacc[nt], af, bf);
            }
        }
        __syncthreads();   // all warps done reading Ks

        if (kt + 1 < nkt) {
            const float* ks = kh + (size_t)(kt + 1) * FA_BN * HD;
            const float* vs = vh + (size_t)(kt + 1) * FA_BN * HD;
            const uint32_t vdst = s_v + (buf ^ 1) * VS_W * 4;
            #pragma unroll
            for (int i = 0; i < 8; i++) {
                int id = tid + i * 256;
                int r = id >> 5, c = (id & 31) << 2;
                cp16(s_k + (r * KS_STRIDE + c) * 4, ks + (size_t)r * HD + c);
                cp16(vdst + (PERM8(r) * VS_STRIDE + c) * 4, vs + (size_t)r * HD + c);
            }
            CP_COMMIT();
        }

        const bool domask = (kt >= 2 * qt);
        #pragma unroll
        for (int i = 0; i < 2; i++) {
            const int qrow = qt * 128 + warp * 16 + g + i * 8;
            float rm = -INFINITY;
            #pragma unroll
            for (int nt = 0; nt < 8; nt++) {
                #pragma unroll
                for (int e = 0; e < 2; e++) {
                    float v = sacc[nt][i * 2 + e] * ATT_SCALE;
                    if (domask && (kt * 64 + nt * 8 + 2 * c4 + e) > qrow) v = -INFINITY;
                    sacc[nt][i * 2 + e] = v;
                    rm = fmaxf(rm, v);
                }
            }
            rm = fmaxf(rm, __shfl_xor_sync(0xffffffffu, rm, 1));
            rm = fmaxf(rm, __shfl_xor_sync(0xffffffffu, rm, 2));
            float mn   = fmaxf(m_i[i], rm);
            float corr = __expf(m_i[i] - mn);
            float rs = 0.f;
            #pragma unroll
            for (int nt = 0; nt < 8; nt++) {
                #pragma unroll
                for (int e = 0; e < 2; e++) {
                    float p = __expf(sacc[nt][i * 2 + e] - mn);
                    rs += p;
                    int jj = 2 * c4 + e;                 // col within 8-block
                    int phys = nt * 8 + PERM8(jj);       // key-permuted store
                    Ps[(warp * 16 + g + i * 8) * PS_STRIDE + phys] = f2tf(p);
                }
            }
            rs += __shfl_xor_sync(0xffffffffu, rs, 1);
            rs += __shfl_xor_sync(0xffffffffu, rs, 2);
            l_i[i] = l_i[i] * corr + rs;
            m_i[i] = mn;
            #pragma unroll
            for (int nt = 0; nt < 16; nt++) {
                oacc[nt][i * 2]     *= corr;
                oacc[nt][i * 2 + 1] *= corr;
            }
        }
        __syncwarp();

        const uint32_t* Vb = Vs + buf * VS_W;
        #pragma unroll
        for (int kk = 0; kk < 8; kk++) {
            const int pc = kk * 8 + c4 * 2;   // permuted pos of keys (kk*8+c4, +4)
            uint32_t af[4];
            {
                uint2 u0 = *(const uint2*)&Pw[g * PS_STRIDE + pc];
                uint2 u1 = *(const uint2*)&Pw[(g + 8) * PS_STRIDE + pc];
                af[0] = u0.x; af[1] = u1.x; af[2] = u0.y; af[3] = u1.y;
            }
            #pragma unroll
            for (int nt = 0; nt < 16; nt++) {
                uint32_t bf[2];
                bf[0] = Vb[pc * VS_STRIDE + nt * 8 + g];
                bf[1] = Vb[(pc + 1) * VS_STRIDE + nt * 8 + g];
                mma_tf32(oacc[nt], af, bf);
            }
        }
        buf ^= 1;
    }

    // ---- finalize; write g_attn k-permuted PER 8-BLOCK (bits 3-4 preserved!) ----
    const int b = bn >> 4, n = bn & 15;
    #pragma unroll
    for (int i = 0; i < 2; i++) {
        float inv = 1.f / l_i[i];
        int row = qt * 128 + warp * 16 + g + i * 8;
        size_t base = ((size_t)b * SS + row) * NHD + (size_t)n * HD;
        #pragma unroll
        for (int nt = 0; nt < 16; nt++) {
            #pragma unroll
            for (int e = 0; e < 2; e++) {
                int col = nt * 8 + 2 * c4 + e;
                int phys = PERM8(col);                   // FIX: was (col & ~31) | ...
                g_attn[base + phys] =
                    __uint_as_float(f2tf(oacc[nt][i * 2 + e] * inv));
            }
        }
    }
}

// =====================================================================
// Decode path (untouched — reads only g_k/g_v/original weights)
// =====================================================================
__global__ void zero_decode() {
    int i = blockIdx.x * 256 + threadIdx.x;
    if (i < BB * NHD) { g_q1[i] = 0.f; g_k1[i] = 0.f; g_v1[i] = 0.f; }
}

__global__ void decode_proj2(const float* __restrict__ xn,
                             const float* __restrict__ wq,
                             const float* __restrict__ wk,
                             const float* __restrict__ wv) {
    int j  = blockIdx.x * 256 + threadIdx.x;
    int d0 = blockIdx.y * 128;
    float aq0=0,aq1=0,ak0=0,ak1=0,av0=0,av1=0;
    #pragma unroll 4
    for (int d = d0; d < d0 + 128; d++) {
        float x0 = xn[d], x1 = xn[DD + d];
        float q = wq[(size_t)d * NHD + j];
        float k = wk[(size_t)d * NHD + j];
        float v = wv[(size_t)d * NHD + j];
        aq0 += x0 * q; aq1 += x1 * q;
        ak0 += x0 * k; ak1 += x1 * k;
        av0 += x0 * v; av1 += x1 * v;
    }
    atomicAdd(&g_q1[j], aq0); atomicAdd(&g_q1[NHD + j], aq1);
    atomicAdd(&g_k1[j], ak0); atomicAdd(&g_k1[NHD + j], ak1);
    atomicAdd(&g_v1[j], av0); atomicAdd(&g_v1[NHD + j], av1);
}

__global__ void dec_attn_split() {
    __shared__ float qsm[HD];
    __shared__ float sc[257];
    __shared__ float red[256];
    const int bn = blockIdx.x, sp = blockIdx.y;
    const int b = bn >> 4, n = bn & 15;
    const int tid = threadIdx.x;
    const int nk = (sp == 7) ? 257 : 256;
    const int base = sp * 256;

    if (tid < HD) qsm[tid] = g_q1[b * NHD + n * HD + tid];
    __syncthreads();

    float lv = -INFINITY;
    for (int j = tid; j < nk; j += 256) {
        int key = base + j;
        const float* kp = (key < SS) ? &g_k[((size_t)bn * SS + key) * HD]
                                     : &g_k1[b * NHD + n * HD];
        float d = 0.f;
        #pragma unroll 8
        for (int h = 0; h < HD; h++) d += qsm[h] * kp[h];
        d *= ATT_SCALE;
        sc[j] = d;
        lv = fmaxf(lv, d);
    }
    red[tid] = lv; __syncthreads();
    for (int o = 128; o; o >>= 1) {
        if (tid < o) red[tid] = fmaxf(red[tid], red[tid + o]);
        __syncthreads();
    }
    const float m = red[0];
    __syncthreads();

    float ls = 0.f;
    for (int j = tid; j < nk; j += 256) {
        float p = __expf(sc[j] - m);
        sc[j] = p;
        ls += p;
    }
    red[tid] = ls; __syncthreads();
    for (int o = 128; o; o >>= 1) {
        if (tid < o) red[tid] += red[tid + o];
        __syncthreads();
    }
    const float l = red[0];
    __syncthreads();

    const int h = tid & 127, half = tid >> 7;
    const int j0 = half ? (nk / 2) : 0;
    const int j1 = half ? nk : (nk / 2);
    float o = 0.f;
    for (int j = j0; j < j1; j++) {
        int key = base + j;
        const float* vp = (key < SS) ? &g_v[((size_t)bn * SS + key) * HD]
                                     : &g_v1[b * NHD + n * HD];
        o += sc[j] * vp[h];
    }
    red[tid] = o; __syncthreads();
    if (tid < HD)
        g_do[(bn * 8 + sp) * HD + tid] = red[tid] + red[128 + tid];
    if (tid == 0) { g_dm[bn * 8 + sp] = m; g_dl[bn * 8 + sp] = l; }
}

__global__ void dec_attn_reduce() {
    const int bn = blockIdx.x, tid = threadIdx.x;
    const int b = bn >> 4, n = bn & 15;
    float m = -INFINITY;
    #pragma unroll
    for (int s = 0; s < 8; s++) m = fmaxf(m, g_dm[bn * 8 + s]);
    float l = 0.f, o = 0.f;
    #pragma unroll
    for (int s = 0; s < 8; s++) {
        float w = __expf(g_dm[bn * 8 + s] - m);
        l += g_dl[bn * 8 + s] * w;
        o += g_do[(bn * 8 + s) * HD + tid] * w;
    }
    g_attn1[b * NHD + n * HD + tid] = o / l;
}

__global__ void decode_outproj(const float* __restrict__ WO, float* __restrict__ out) {
    int gw   = (blockIdx.x * 256 + threadIdx.x) >> 5;
    int lane = threadIdx.x & 31;
    int b = gw >> 11, d = gw & 2047;
    const float* a = g_attn1 + (size_t)b * NHD;
    const float* w = WO + (size_t)d * NHD;
    float acc = 0.f;
    for (int k = lane; k < NHD; k += 32) acc += a[k] * w[k];
    #pragma unroll
    for (int o = 16; o; o >>= 1) acc += __shfl_xor_sync(0xffffffffu, acc, o);
    if (lane == 0) out[(size_t)b * DD + d] = acc;
}

// =====================================================================
// launch
// =====================================================================
extern "C" void kernel_launch(void* const* d_in, const int* in_sizes, int n_in,
                              void* d_out, int out_size) {
    const float* x   = (const float*)d_in[0];
    const float* xn  = (const float*)d_in[1];
    const float* wq  = (const float*)d_in[2];
    const float* wk  = (const float*)d_in[3];
    const float* wv  = (const float*)d_in[4];
    const float* wo  = (const float*)d_in[5];
    float* out = (float*)d_out;

    cudaFuncSetAttribute((const void*)flash_attn_tc,
                         cudaFuncAttributeMaxDynamicSharedMemorySize, FA_SMEM_BYTES);
    cudaFuncSetAttribute((const void*)mma_gemm<0>,
                         cudaFuncAttributeMaxDynamicSharedMemorySize, GEMM_SMEM_NN);
    cudaFuncSetAttribute((const void*)mma_gemm<1>,
                         cudaFuncAttributeMaxDynamicSharedMemorySize, GEMM_SMEM_NT);

    zero_decode<<<16, 256>>>();
    preround<<<dim3(8192, 5), 256>>>(x, wq, wk, wv, wo);
    decode_proj2<<<dim3(8, 16), 256>>>(xn, wq, wk, wv);

    mma_gemm<0><<<dim3(16, 32, 3), 256, GEMM_SMEM_NN>>>(nullptr);  // fused QKV

    flash_attn_tc<<<dim3(16, 32), 256, FA_SMEM_BYTES>>>();

    mma_gemm<1><<<dim3(16, 32, 1), 256, GEMM_SMEM_NT>>>(out);      // out-proj

    dec_attn_split<<<dim3(32, 8), 256>>>();
    dec_attn_reduce<<<32, 128>>>();
    decode_outproj<<<512, 256>>>(wo, out + PREFILL_ELEMS);
}

// round 12
// speedup vs baseline: 1.2051x; 1.2051x over previous
#include <cuda_runtime.h>
#include <cstdint>

// ---------------- problem constants ----------------
#define BB   2
#define SS   2048
#define DD   2048
#define NHN  16
#define HD   128
#define NHD  2048              // NHN*HD
#define MM   (BB*SS)           // 4096 rows for prefill GEMMs
#define ATT_SCALE 0.08838834764831845f   // 1/sqrt(128)
#define PREFILL_ELEMS (BB*SS*DD)         // 8388608

// perm within each 8-block of k: k -> (k&~7) | ((k&3)<<1) | ((k>>2)&1)
// pairs original (k, k+4) at adjacent addresses.
// inverse (within 32-block): p -> (p&24) | ((p&1)<<2) | ((p>>1)&3)
#define INV32(p) (((p) & 24) | (((p) & 1) << 2) | (((p) >> 1) & 3))
#define PERM8(k) (((k) & ~7) | (((k) & 3) << 1) | (((k) >> 2) & 1))

// ---------------- scratch (device globals; no allocation allowed) ----------------
__device__ float g_q[(size_t)BB*NHN*SS*HD];   // [B,N,S,H] (tf32-rounded)
__device__ float g_k[(size_t)BB*NHN*SS*HD];
__device__ float g_v[(size_t)BB*NHN*SS*HD];
__device__ float g_attn[(size_t)BB*SS*NHD];   // [B,S,N*H] tf32, k-permuted per 8-block
__device__ float g_q1[BB*NHD];
__device__ float g_k1[BB*NHD];
__device__ float g_v1[BB*NHD];
__device__ float g_attn1[BB*NHD];
// decode split-K partials
__device__ float g_dm[32*8];
__device__ float g_dl[32*8];
__device__ float g_do[32*8*HD];
// tf32-pre-rounded inputs (g_xt, g_wot additionally k-permuted)
__device__ float g_xt[(size_t)MM*DD];
__device__ float g_wqt[(size_t)DD*NHD];
__device__ float g_wkt[(size_t)DD*NHD];
__device__ float g_wvt[(size_t)DD*NHD];
__device__ float g_wot[(size_t)DD*NHD];

// =====================================================================
// tf32 / cp.async helpers
// =====================================================================
__device__ __forceinline__ uint32_t f2tf(float f) {
    uint32_t u;
    asm("cvt.rna.tf32.f32 %0, %1;" : "=r"(u) : "f"(f));
    return u;
}

__device__ __forceinline__ void mma_tf32(float* c, const uint32_t* a, const uint32_t* b) {
    asm volatile(
        "mma.sync.aligned.m16n8k8.row.col.f32.tf32.tf32.f32 "
        "{%0,%1,%2,%3}, {%4,%5,%6,%7}, {%8,%9}, {%0,%1,%2,%3};"
        : "+f"(c[0]), "+f"(c[1]), "+f"(c[2]), "+f"(c[3])
        : "r"(a[0]), "r"(a[1]), "r"(a[2]), "r"(a[3]), "r"(b[0]), "r"(b[1]));
}

__device__ __forceinline__ void cp16(uint32_t dst_smem, const void* src) {
    asm volatile("cp.async.cg.shared.global [%0], [%1], 16;"
                 :: "r"(dst_smem), "l"(src));
}
#define CP_COMMIT() asm volatile("cp.async.commit_group;" ::: "memory")
#define CP_WAIT(N)  asm volatile("cp.async.wait_group %0;" :: "n"(N) : "memory")

// =====================================================================
// pre-round to tf32; segs 0 (x) and 4 (wo) additionally k-permuted.
// =====================================================================
__global__ void preround(const float* __restrict__ x,  const float* __restrict__ wq,
                         const float* __restrict__ wk, const float* __restrict__ wv,
                         const float* __restrict__ wo) {
    int t = blockIdx.x * 256 + threadIdx.x;
    int seg = blockIdx.y;
    const float* s; float* d; int n4; bool prm;
    if (seg == 0)      { s = x;  d = g_xt;  n4 = (MM*DD) / 4; prm = true;  }
    else if (seg == 1) { s = wq; d = g_wqt; n4 = (DD*NHD) / 4; prm = false; }
    else if (seg == 2) { s = wk; d = g_wkt; n4 = (DD*NHD) / 4; prm = false; }
    else if (seg == 3) { s = wv; d = g_wvt; n4 = (DD*NHD) / 4; prm = false; }
    else               { s = wo; d = g_wot; n4 = (DD*NHD) / 4; prm = true;  }
    if (t >= n4) return;
    if (!prm) {
        float4 v = ((const float4*)s)[t];
        ((uint4*)d)[t] = make_uint4(f2tf(v.x), f2tf(v.y), f2tf(v.z), f2tf(v.w));
    } else {
        int e0 = t * 4;
        uint32_t o[4];
        #pragma unroll
        for (int u = 0; u < 4; u++) {
            int e = e0 + u, c = e & 31;
            o[u] = f2tf(s[(e & ~31) + INV32(c)]);
        }
        ((uint4*)d)[t] = make_uint4(o[0], o[1], o[2], o[3]);
    }
}

// =====================================================================
// tf32 tensor-core GEMM. CTA 128x128x32, warp tile 64x32 (2Mx4N),
// cp.async pipeline (NN: 3-stage, NT: 2-stage).  k-permuted layouts;
// CONFLICT-FREE strides: A/NT-B = 40, NN-B = 140.
// NT=0 (QKV fused by z): A=g_xt(perm), B=W [k][n] row-remapped at load;
//                        scatter to g_q/g_k/g_v (normal layout).
// NT=1 (out-proj): A=g_attn(perm), B=g_wot [n][k](perm); C -> out fp32.
// =====================================================================
#define AS_STR  40
#define AS_W    (128*AS_STR)        // 5120
#define BNN_STR 140
#define BNN_W   (32*BNN_STR)        // 4480
#define BNT_W   (128*AS_STR)        // 5120
#define GEMM_SMEM_NN ((3*(AS_W + BNN_W))*4)   // 115200
#define GEMM_SMEM_NT ((2*(AS_W + BNT_W))*4)   // 81920

template<int NT>
__global__ __launch_bounds__(256, 2) void mma_gemm(float* __restrict__ out) {
    extern __shared__ uint32_t smw[];
    constexpr int ST = NT ? 2 : 3;
    constexpr int BW = NT ? BNT_W : BNN_W;
    uint32_t* Asm = smw;
    uint32_t* Bsm = smw + ST * AS_W;
    const uint32_t sa_base = (uint32_t)__cvta_generic_to_shared(smw);
    const uint32_t sb_base = sa_base + ST * AS_W * 4;

    const int z = blockIdx.z;
    const float* A    = NT ? g_attn : g_xt;
    const float* Bsrc = NT ? g_wot
                      : (z == 0) ? g_wqt : (z == 1) ? g_wkt : g_wvt;

    const int tid = threadIdx.x;
    const int m0 = blockIdx.y * 128, n0 = blockIdx.x * 128;
    const int warp = tid >> 5, lane = tid & 31;
    const int wm = warp >> 2, wn = warp & 3;   // 2(M) x 4(N), warp tile 64x32
    const int g  = lane >> 2, c4 = lane & 3;

    float acc[4][4][4];
    #pragma unroll
    for (int i = 0; i < 4; i++)
        #pragma unroll
        for (int j = 0; j < 4; j++)
            #pragma unroll
            for (int e = 0; e < 4; e++) acc[i][j][e] = 0.f;

    auto load_stage = [&](int st, int kt) {
        uint32_t ab = sa_base + st * AS_W * 4;
        const float* asrc = A + (size_t)m0 * DD + (size_t)kt * 32;
        #pragma unroll
        for (int i = 0; i < 4; i++) {
            int id = tid + i * 256;
            int row = id >> 3, co = (id & 7) << 2;
            cp16(ab + (row * AS_STR + co) * 4, asrc + (size_t)row * DD + co);
        }
        uint32_t bb = sb_base + st * BW * 4;
        if (!NT) {
            // smem row kr holds gmem row kt*32 + INV32(kr)
            const float* bs = Bsrc + (size_t)kt * 32 * NHD + n0;
            #pragma unroll
            for (int i = 0; i < 4; i++) {
                int id = tid + i * 256;
                int kr = id >> 5, co = (id & 31) << 2;
                int src = INV32(kr);
                cp16(bb + (kr * BNN_STR + co) * 4, bs + (size_t)src * NHD + co);
            }
        } else {
            const float* bs = Bsrc + (size_t)n0 * NHD + (size_t)kt * 32;
            #pragma unroll
            for (int i = 0; i < 4; i++) {
                int id = tid + i * 256;
                int nr = id >> 3, co = (id & 7) << 2;
                cp16(bb + (nr * AS_STR + co) * 4, bs + (size_t)nr * NHD + co);
            }
        }
        CP_COMMIT();
    };

    auto compute = [&](int st) {
        const uint32_t* Ab = Asm + st * AS_W + (wm * 64) * AS_STR;
        const uint32_t* Bb = Bsm + st * BW;
        #pragma unroll
        for (int kk = 0; kk < 4; kk++) {
            const int pc = kk * 8 + c4 * 2;   // permuted position of (kk*8+c4, +4)
            uint32_t af[4][4];
            #pragma unroll
            for (int i = 0; i < 4; i++) {
                int r = i * 16 + g;
                uint2 u0 = *(const uint2*)&Ab[r * AS_STR + pc];
                uint2 u1 = *(const uint2*)&Ab[(r + 8) * AS_STR + pc];
                af[i][0] = u0.x; af[i][1] = u1.x; af[i][2] = u0.y; af[i][3] = u1.y;
            }
            #pragma unroll
            for (int j = 0; j < 4; j++) {
                uint32_t bf[2];
                if (!NT) {
                    bf[0] = Bb[pc * BNN_STR + wn * 32 + j * 8 + g];
                    bf[1] = Bb[(pc + 1) * BNN_STR + wn * 32 + j * 8 + g];
                } else {
                    uint2 ub = *(const uint2*)&Bb[(wn * 32 + j * 8 + g) * AS_STR + pc];
                    bf[0] = ub.x; bf[1] = ub.y;
                }
                #pragma unroll
                for (int i = 0; i < 4; i++)
                    mma_tf32(acc[i][j], af[i], bf);
            }
        }
    };

    load_stage(0, 0);
    load_stage(1, 1);
    for (int kt = 0; kt < 64; kt++) {
        if (kt < 63) CP_WAIT(1); else CP_WAIT(0);
        __syncthreads();
        if (!NT) {
            if (kt + 2 < 64) load_stage((kt + 2) % 3, kt + 2);
            compute(kt % 3);
        } else {
            compute(kt & 1);
            if (kt + 2 < 64) {
                __syncthreads();          // all warps done reading this buffer
                load_stage(kt & 1, kt + 2);
            }
        }
    }

    if (!NT) {
        const int head = blockIdx.x;   // BN=128 == HD
        float* dst = (z == 0) ? g_q : (z == 1) ? g_k : g_v;
        #pragma unroll
        for (int i = 0; i < 4; i++) {
            int m = m0 + wm * 64 + i * 16 + g;
            int b = m >> 11, s = m & 2047;
            #pragma unroll
            for (int j = 0; j < 4; j++) {
                int h = wn * 32 + j * 8 + 2 * c4;
                size_t o = ((size_t)(b * NHN + head) * SS + s) * HD + h;
                *(float2*)&dst[o] = make_float2(__uint_as_float(f2tf(acc[i][j][0])),
                                                __uint_as_float(f2tf(acc[i][j][1])));
                *(float2*)&dst[o + 8 * HD] = make_float2(__uint_as_float(f2tf(acc[i][j][2])),
                                                         __uint_as_float(f2tf(acc[i][j][3])));
            }
        }
    } else {
        #pragma unroll
        for (int i = 0; i < 4; i++) {
            int m = m0 + wm * 64 + i * 16 + g;
            #pragma unroll
            for (int j = 0; j < 4; j++) {
                int col = n0 + wn * 32 + j * 8 + 2 * c4;
                *(float2*)&out[(size_t)m * DD + col] =
                    make_float2(acc[i][j][0], acc[i][j][1]);
                *(float2*)&out[(size_t)(m + 8) * DD + col] =
                    make_float2(acc[i][j][2], acc[i][j][3]);
            }
        }
    }
}

// =====================================================================
// tf32 tensor-core flash attention (prefill, causal).
// K prefetch + double-buffered V.  P stored key-permuted (stride 72) +
// V smem rows key-permuted (stride 140) -> conflict-free LDS.64 P frags.
// Epilogue writes g_attn k-permuted per 8-block (consumed by NT GEMM).
// =====================================================================
#define FA_BM 128
#define FA_BN 64
#define QS_STRIDE 132
#define KS_STRIDE 132
#define VS_STRIDE 140
#define PS_STRIDE 72
#define QS_SIZE (FA_BM*QS_STRIDE)
#define KS_SIZE (FA_BN*KS_STRIDE)
#define VS_W    (FA_BN*VS_STRIDE)
#define PS_SIZE (FA_BM*PS_STRIDE)
#define FA_SMEM_BYTES ((QS_SIZE+KS_SIZE+2*VS_W+PS_SIZE)*4)   // 209920

__global__ __launch_bounds__(256, 1) void flash_attn_tc() {
    extern __shared__ uint32_t smu[];
    uint32_t* Qs = smu;
    uint32_t* Ks = smu + QS_SIZE;
    uint32_t* Vs = Ks + KS_SIZE;            // two buffers of VS_W
    uint32_t* Ps = Vs + 2 * VS_W;
    const uint32_t s_q = (uint32_t)__cvta_generic_to_shared(smu);
    const uint32_t s_k = s_q + QS_SIZE * 4;
    const uint32_t s_v = s_k + KS_SIZE * 4;

    const int qt  = blockIdx.x;
    const int bn  = blockIdx.y;
    const int tid = threadIdx.x;
    const int warp = tid >> 5, lane = tid & 31;
    const int g = lane >> 2, c4 = lane & 3;

    const float* qh = g_q + (size_t)bn * SS * HD;
    const float* kh = g_k + (size_t)bn * SS * HD;
    const float* vh = g_v + (size_t)bn * SS * HD;

    {
        const float* src = qh + (size_t)qt * FA_BM * HD;
        #pragma unroll
        for (int i = 0; i < 16; i++) {
            int id = tid + i * 256;
            int r = id >> 5, c = (id & 31) << 2;
            cp16(s_q + (r * QS_STRIDE + c) * 4, src + (size_t)r * HD + c);
        }
        CP_COMMIT();
    }
    {
        #pragma unroll
        for (int i = 0; i < 8; i++) {
            int id = tid + i * 256;
            int r = id >> 5, c = (id & 31) << 2;
            cp16(s_k + (r * KS_STRIDE + c) * 4, kh + (size_t)r * HD + c);
            cp16(s_v + (PERM8(r) * VS_STRIDE + c) * 4, vh + (size_t)r * HD + c);
        }
        CP_COMMIT();
    }

    float m_i[2] = {-INFINITY, -INFINITY};
    float l_i[2] = {0.f, 0.f};
    float oacc[16][4];
    #pragma unroll
    for (int nt = 0; nt < 16; nt++)
        #pragma unroll
        for (int e = 0; e < 4; e++) oacc[nt][e] = 0.f;

    const int nkt = 2 * qt + 2;
    const uint32_t* Qw = Qs + (warp * 16) * QS_STRIDE;
    const uint32_t* Pw = Ps + (warp * 16) * PS_STRIDE;
    int buf = 0;

    for (int kt = 0; kt < nkt; kt++) {
        CP_WAIT(0);
        __syncthreads();

        float sacc[8][4];
        #pragma unroll
        for (int nt = 0; nt < 8; nt++)
            #pragma unroll
            for (int e = 0; e < 4; e++) sacc[nt][e] = 0.f;

        #pragma unroll
        for (int kk = 0; kk < 16; kk++) {
            const int cb = kk * 8 + c4;
            uint32_t af[4];
            af[0] = Qw[g * QS_STRIDE + cb];
            af[1] = Qw[(g + 8) * QS_STRIDE + cb];
            af[2] = Qw[g * QS_STRIDE + cb + 4];
            af[3] = Qw[(g + 8) * QS_STRIDE + cb + 4];
            #pragma unroll
            for (int nt = 0; nt < 8; nt++) {
                uint32_t bf[2];
                bf[0] = Ks[(nt * 8 + g) * KS_STRIDE + cb];
                bf[1] = Ks[(nt * 8 + g) * KS_STRIDE + cb + 4];
                mma_tf32(sacc[nt], af, bf);
            }
        }
        __syncthreads();   // all warps done reading Ks

        if (kt + 1 < nkt) {
            const float* ks = kh + (size_t)(kt + 1) * FA_BN * HD;
            const float* vs = vh + (size_t)(kt + 1) * FA_BN * HD;
            const uint32_t vdst = s_v + (buf ^ 1) * VS_W * 4;
            #pragma unroll
            for (int i = 0; i < 8; i++) {
                int id = tid + i * 256;
                int r = id >> 5, c = (id & 31) << 2;
                cp16(s_k + (r * KS_STRIDE + c) * 4, ks + (size_t)r * HD + c);
                cp16(vdst + (PERM8(r) * VS_STRIDE + c) * 4, vs + (size_t)r * HD + c);
            }
            CP_COMMIT();
        }

        const bool domask = (kt >= 2 * qt);
        #pragma unroll
        for (int i = 0; i < 2; i++) {
            const int qrow = qt * 128 + warp * 16 + g + i * 8;
            float rm = -INFINITY;
            #pragma unroll
            for (int nt = 0; nt < 8; nt++) {
                #pragma unroll
                for (int e = 0; e < 2; e++) {
                    float v = sacc[nt][i * 2 + e] * ATT_SCALE;
                    if (domask && (kt * 64 + nt * 8 + 2 * c4 + e) > qrow) v = -INFINITY;
                    sacc[nt][i * 2 + e] = v;
                    rm = fmaxf(rm, v);
                }
            }
            rm = fmaxf(rm, __shfl_xor_sync(0xffffffffu, rm, 1));
            rm = fmaxf(rm, __shfl_xor_sync(0xffffffffu, rm, 2));
            float mn   = fmaxf(m_i[i], rm);
            float corr = __expf(m_i[i] - mn);
            float rs = 0.f;
            #pragma unroll
            for (int nt = 0; nt < 8; nt++) {
                #pragma unroll
                for (int e = 0; e < 2; e++) {
                    float p = __expf(sacc[nt][i * 2 + e] - mn);
                    rs += p;
                    int jj = 2 * c4 + e;                 // col within 8-block
                    int phys = nt * 8 + PERM8(jj);       // key-permuted store
                    Ps[(warp * 16 + g + i * 8) * PS_STRIDE + phys] = f2tf(p);
                }
            }
            rs += __shfl_xor_sync(0xffffffffu, rs, 1);
            rs += __shfl_xor_sync(0xffffffffu, rs, 2);
            l_i[i] = l_i[i] * corr + rs;
            m_i[i] = mn;
            #pragma unroll
            for (int nt = 0; nt < 16; nt++) {
                oacc[nt][i * 2]     *= corr;
                oacc[nt][i * 2 + 1] *= corr;
            }
        }
        __syncwarp();

        const uint32_t* Vb = Vs + buf * VS_W;
        #pragma unroll
        for (int kk = 0; kk < 8; kk++) {
            const int pc = kk * 8 + c4 * 2;   // permuted pos of keys (kk*8+c4, +4)
            uint32_t af[4];
            {
                uint2 u0 = *(const uint2*)&Pw[g * PS_STRIDE + pc];
                uint2 u1 = *(const uint2*)&Pw[(g + 8) * PS_STRIDE + pc];
                af[0] = u0.x; af[1] = u1.x; af[2] = u0.y; af[3] = u1.y;
            }
            #pragma unroll
            for (int nt = 0; nt < 16; nt++) {
                uint32_t bf[2];
                bf[0] = Vb[pc * VS_STRIDE + nt * 8 + g];
                bf[1] = Vb[(pc + 1) * VS_STRIDE + nt * 8 + g];
                mma_tf32(oacc[nt], af, bf);
            }
        }
        buf ^= 1;
    }

    // ---- finalize; write g_attn k-permuted per 8-block ----
    const int b = bn >> 4, n = bn & 15;
    #pragma unroll
    for (int i = 0; i < 2; i++) {
        float inv = 1.f / l_i[i];
        int row = qt * 128 + warp * 16 + g + i * 8;
        size_t base = ((size_t)b * SS + row) * NHD + (size_t)n * HD;
        #pragma unroll
        for (int nt = 0; nt < 16; nt++) {
            #pragma unroll
            for (int e = 0; e < 2; e++) {
                int col = nt * 8 + 2 * c4 + e;
                int phys = PERM8(col);
                g_attn[base + phys] =
                    __uint_as_float(f2tf(oacc[nt][i * 2 + e] * inv));
            }
        }
    }
}

// =====================================================================
// Decode path (untouched — reads only g_k/g_v/original weights)
// =====================================================================
__global__ void zero_decode() {
    int i = blockIdx.x * 256 + threadIdx.x;
    if (i < BB * NHD) { g_q1[i] = 0.f; g_k1[i] = 0.f; g_v1[i] = 0.f; }
}

__global__ void decode_proj2(const float* __restrict__ xn,
                             const float* __restrict__ wq,
                             const float* __restrict__ wk,
                             const float* __restrict__ wv) {
    int j  = blockIdx.x * 256 + threadIdx.x;
    int d0 = blockIdx.y * 128;
    float aq0=0,aq1=0,ak0=0,ak1=0,av0=0,av1=0;
    #pragma unroll 4
    for (int d = d0; d < d0 + 128; d++) {
        float x0 = xn[d], x1 = xn[DD + d];
        float q = wq[(size_t)d * NHD + j];
        float k = wk[(size_t)d * NHD + j];
        float v = wv[(size_t)d * NHD + j];
        aq0 += x0 * q; aq1 += x1 * q;
        ak0 += x0 * k; ak1 += x1 * k;
        av0 += x0 * v; av1 += x1 * v;
    }
    atomicAdd(&g_q1[j], aq0); atomicAdd(&g_q1[NHD + j], aq1);
    atomicAdd(&g_k1[j], ak0); atomicAdd(&g_k1[NHD + j], ak1);
    atomicAdd(&g_v1[j], av0); atomicAdd(&g_v1[NHD + j], av1);
}

__global__ void dec_attn_split() {
    __shared__ float qsm[HD];
    __shared__ float sc[257];
    __shared__ float red[256];
    const int bn = blockIdx.x, sp = blockIdx.y;
    const int b = bn >> 4, n = bn & 15;
    const int tid = threadIdx.x;
    const int nk = (sp == 7) ? 257 : 256;
    const int base = sp * 256;

    if (tid < HD) qsm[tid] = g_q1[b * NHD + n * HD + tid];
    __syncthreads();

    float lv = -INFINITY;
    for (int j = tid; j < nk; j += 256) {
        int key = base + j;
        const float* kp = (key < SS) ? &g_k[((size_t)bn * SS + key) * HD]
                                     : &g_k1[b * NHD + n * HD];
        float d = 0.f;
        #pragma unroll 8
        for (int h = 0; h < HD; h++) d += qsm[h] * kp[h];
        d *= ATT_SCALE;
        sc[j] = d;
        lv = fmaxf(lv, d);
    }
    red[tid] = lv; __syncthreads();
    for (int o = 128; o; o >>= 1) {
        if (tid < o) red[tid] = fmaxf(red[tid], red[tid + o]);
        __syncthreads();
    }
    const float m = red[0];
    __syncthreads();

    float ls = 0.f;
    for (int j = tid; j < nk; j += 256) {
        float p = __expf(sc[j] - m);
        sc[j] = p;
        ls += p;
    }
    red[tid] = ls; __syncthreads();
    for (int o = 128; o; o >>= 1) {
        if (tid < o) red[tid] += red[tid + o];
        __syncthreads();
    }
    const float l = red[0];
    __syncthreads();

    const int h = tid & 127, half = tid >> 7;
    const int j0 = half ? (nk / 2) : 0;
    const int j1 = half ? nk : (nk / 2);
    float o = 0.f;
    for (int j = j0; j < j1; j++) {
        int key = base + j;
        const float* vp = (key < SS) ? &g_v[((size_t)bn * SS + key) * HD]
                                     : &g_v1[b * NHD + n * HD];
        o += sc[j] * vp[h];
    }
    red[tid] = o; __syncthreads();
    if (tid < HD)
        g_do[(bn * 8 + sp) * HD + tid] = red[tid] + red[128 + tid];
    if (tid == 0) { g_dm[bn * 8 + sp] = m; g_dl[bn * 8 + sp] = l; }
}

__global__ void dec_attn_reduce() {
    const int bn = blockIdx.x, tid = threadIdx.x;
    const int b = bn >> 4, n = bn & 15;
    float m = -INFINITY;
    #pragma unroll
    for (int s = 0; s < 8; s++) m = fmaxf(m, g_dm[bn * 8 + s]);
    float l = 0.f, o = 0.f;
    #pragma unroll
    for (int s = 0; s < 8; s++) {
        float w = __expf(g_dm[bn * 8 + s] - m);
        l += g_dl[bn * 8 + s] * w;
        o += g_do[(bn * 8 + s) * HD + tid] * w;
    }
    g_attn1[b * NHD + n * HD + tid] = o / l;
}

__global__ void decode_outproj(const float* __restrict__ WO, float* __restrict__ out) {
    int gw   = (blockIdx.x * 256 + threadIdx.x) >> 5;
    int lane = threadIdx.x & 31;
    int b = gw >> 11, d = gw & 2047;
    const float* a = g_attn1 + (size_t)b * NHD;
    const float* w = WO + (size_t)d * NHD;
    float acc = 0.f;
    for (int k = lane; k < NHD; k += 32) acc += a[k] * w[k];
    #pragma unroll
    for (int o = 16; o; o >>= 1) acc += __shfl_xor_sync(0xffffffffu, acc, o);
    if (lane == 0) out[(size_t)b * DD + d] = acc;
}

// =====================================================================
// launch
// =====================================================================
extern "C" void kernel_launch(void* const* d_in, const int* in_sizes, int n_in,
                              void* d_out, int out_size) {
    const float* x   = (const float*)d_in[0];
    const float* xn  = (const float*)d_in[1];
    const float* wq  = (const float*)d_in[2];
    const float* wk  = (const float*)d_in[3];
    const float* wv  = (const float*)d_in[4];
    const float* wo  = (const float*)d_in[5];
    float* out = (float*)d_out;

    cudaFuncSetAttribute((const void*)flash_attn_tc,
                         cudaFuncAttributeMaxDynamicSharedMemorySize, FA_SMEM_BYTES);
    cudaFuncSetAttribute((const void*)mma_gemm<0>,
                         cudaFuncAttributeMaxDynamicSharedMemorySize, GEMM_SMEM_NN);
    cudaFuncSetAttribute((const void*)mma_gemm<1>,
                         cudaFuncAttributeMaxDynamicSharedMemorySize, GEMM_SMEM_NT);

    zero_decode<<<16, 256>>>();
    preround<<<dim3(8192, 5), 256>>>(x, wq, wk, wv, wo);
    decode_proj2<<<dim3(8, 16), 256>>>(xn, wq, wk, wv);

    mma_gemm<0><<<dim3(16, 32, 3), 256, GEMM_SMEM_NN>>>(nullptr);  // fused QKV

    flash_attn_tc<<<dim3(16, 32), 256, FA_SMEM_BYTES>>>();

    mma_gemm<1><<<dim3(16, 32, 1), 256, GEMM_SMEM_NT>>>(out);      // out-proj

    dec_attn_split<<<dim3(32, 8), 256>>>();
    dec_attn_reduce<<<32, 128>>>();
    decode_outproj<<<512, 256>>>(wo, out + PREFILL_ELEMS);
}

// round 15
// speedup vs baseline: 1.2780x; 1.0604x over previous
#include <cuda_runtime.h>
#include <cstdint>

// ---------------- problem constants ----------------
#define BB   2
#define SS   2048
#define DD   2048
#define NHN  16
#define HD   128
#define NHD  2048              // NHN*HD
#define MM   (BB*SS)           // 4096 rows for prefill GEMMs
#define ATT_SCALE 0.08838834764831845f   // 1/sqrt(128)
#define PREFILL_ELEMS (BB*SS*DD)         // 8388608

// perm within each 8-block of k: k -> (k&~7) | ((k&3)<<1) | ((k>>2)&1)
// pairs original (k, k+4) at adjacent addresses.
// inverse (within 32-block): p -> (p&24) | ((p&1)<<2) | ((p>>1)&3)
#define INV32(p) (((p) & 24) | (((p) & 1) << 2) | (((p) >> 1) & 3))
#define PERM8(k) (((k) & ~7) | (((k) & 3) << 1) | (((k) >> 2) & 1))

// ---------------- scratch (device globals; no allocation allowed) ----------------
__device__ float g_q[(size_t)BB*NHN*SS*HD];   // [B,N,S,H] (tf32-rounded)
__device__ float g_k[(size_t)BB*NHN*SS*HD];
__device__ float g_v[(size_t)BB*NHN*SS*HD];
__device__ float g_attn[(size_t)BB*SS*NHD];   // [B,S,N*H] tf32, k-permuted per 8-block
__device__ float g_q1[BB*NHD];
__device__ float g_k1[BB*NHD];
__device__ float g_v1[BB*NHD];
__device__ float g_attn1[BB*NHD];
// decode split-K partials
__device__ float g_dm[32*8];
__device__ float g_dl[32*8];
__device__ float g_do[32*8*HD];
// tf32-pre-rounded inputs (g_xt, g_wot additionally k-permuted)
__device__ float g_xt[(size_t)MM*DD];
__device__ float g_wqt[(size_t)DD*NHD];
__device__ float g_wkt[(size_t)DD*NHD];
__device__ float g_wvt[(size_t)DD*NHD];
__device__ float g_wot[(size_t)DD*NHD];

// =====================================================================
// tf32 / cp.async helpers
// =====================================================================
__device__ __forceinline__ uint32_t f2tf(float f) {
    uint32_t u;
    asm("cvt.rna.tf32.f32 %0, %1;" : "=r"(u) : "f"(f));
    return u;
}

__device__ __forceinline__ void mma_tf32(float* c, const uint32_t* a, const uint32_t* b) {
    asm volatile(
        "mma.sync.aligned.m16n8k8.row.col.f32.tf32.tf32.f32 "
        "{%0,%1,%2,%3}, {%4,%5,%6,%7}, {%8,%9}, {%0,%1,%2,%3};"
        : "+f"(c[0]), "+f"(c[1]), "+f"(c[2]), "+f"(c[3])
        : "r"(a[0]), "r"(a[1]), "r"(a[2]), "r"(a[3]), "r"(b[0]), "r"(b[1]));
}

__device__ __forceinline__ void cp16(uint32_t dst_smem, const void* src) {
    asm volatile("cp.async.cg.shared.global [%0], [%1], 16;"
                 :: "r"(dst_smem), "l"(src));
}
#define CP_COMMIT() asm volatile("cp.async.commit_group;" ::: "memory")
#define CP_WAIT(N)  asm volatile("cp.async.wait_group %0;" :: "n"(N) : "memory")

// =====================================================================
// pre-round to tf32; segs 0 (x) and 4 (wo) additionally k-permuted.
// =====================================================================
__global__ void preround(const float* __restrict__ x,  const float* __restrict__ wq,
                         const float* __restrict__ wk, const float* __restrict__ wv,
                         const float* __restrict__ wo) {
    int t = blockIdx.x * 256 + threadIdx.x;
    int seg = blockIdx.y;
    const float* s; float* d; int n4; bool prm;
    if (seg == 0)      { s = x;  d = g_xt;  n4 = (MM*DD) / 4; prm = true;  }
    else if (seg == 1) { s = wq; d = g_wqt; n4 = (DD*NHD) / 4; prm = false; }
    else if (seg == 2) { s = wk; d = g_wkt; n4 = (DD*NHD) / 4; prm = false; }
    else if (seg == 3) { s = wv; d = g_wvt; n4 = (DD*NHD) / 4; prm = false; }
    else               { s = wo; d = g_wot; n4 = (DD*NHD) / 4; prm = true;  }
    if (t >= n4) return;
    if (!prm) {
        float4 v = ((const float4*)s)[t];
        ((uint4*)d)[t] = make_uint4(f2tf(v.x), f2tf(v.y), f2tf(v.z), f2tf(v.w));
    } else {
        int e0 = t * 4;
        uint32_t o[4];
        #pragma unroll
        for (int u = 0; u < 4; u++) {
            int e = e0 + u, c = e & 31;
            o[u] = f2tf(s[(e & ~31) + INV32(c)]);
        }
        ((uint4*)d)[t] = make_uint4(o[0], o[1], o[2], o[3]);
    }
}

// =====================================================================
// tf32 tensor-core GEMM. CTA 128x128x32, warp tile 64x32 (2Mx4N),
// cp.async pipeline (NN: 3-stage, NT: 2-stage).  k-permuted layouts;
// conflict-free strides: A/NT-B = 40, NN-B = 140.
// NT=0 (QKV fused by z): A=g_xt(perm), B=W [k][n] row-remapped at load;
//                        scatter to g_q/g_k/g_v (normal layout).
// NT=1 (out-proj): A=g_attn(perm), B=g_wot [n][k](perm); C -> out fp32.
// =====================================================================
#define AS_STR  40
#define AS_W    (128*AS_STR)        // 5120
#define BNN_STR 140
#define BNN_W   (32*BNN_STR)        // 4480
#define BNT_W   (128*AS_STR)        // 5120
#define GEMM_SMEM_NN ((3*(AS_W + BNN_W))*4)   // 115200
#define GEMM_SMEM_NT ((2*(AS_W + BNT_W))*4)   // 81920

template<int NT>
__global__ __launch_bounds__(256, 2) void mma_gemm(float* __restrict__ out) {
    extern __shared__ uint32_t smw[];
    constexpr int ST = NT ? 2 : 3;
    constexpr int BW = NT ? BNT_W : BNN_W;
    uint32_t* Asm = smw;
    uint32_t* Bsm = smw + ST * AS_W;
    const uint32_t sa_base = (uint32_t)__cvta_generic_to_shared(smw);
    const uint32_t sb_base = sa_base + ST * AS_W * 4;

    const int z = blockIdx.z;
    const float* A    = NT ? g_attn : g_xt;
    const float* Bsrc = NT ? g_wot
                      : (z == 0) ? g_wqt : (z == 1) ? g_wkt : g_wvt;

    const int tid = threadIdx.x;
    const int m0 = blockIdx.y * 128, n0 = blockIdx.x * 128;
    const int warp = tid >> 5, lane = tid & 31;
    const int wm = warp >> 2, wn = warp & 3;   // 2(M) x 4(N), warp tile 64x32
    const int g  = lane >> 2, c4 = lane & 3;

    float acc[4][4][4];
    #pragma unroll
    for (int i = 0; i < 4; i++)
        #pragma unroll
        for (int j = 0; j < 4; j++)
            #pragma unroll
            for (int e = 0; e < 4; e++) acc[i][j][e] = 0.f;

    auto load_stage = [&](int st, int kt) {
        uint32_t ab = sa_base + st * AS_W * 4;
        const float* asrc = A + (size_t)m0 * DD + (size_t)kt * 32;
        #pragma unroll
        for (int i = 0; i < 4; i++) {
            int id = tid + i * 256;
            int row = id >> 3, co = (id & 7) << 2;
            cp16(ab + (row * AS_STR + co) * 4, asrc + (size_t)row * DD + co);
        }
        uint32_t bb = sb_base + st * BW * 4;
        if (!NT) {
            // smem row kr holds gmem row kt*32 + INV32(kr)
            const float* bs = Bsrc + (size_t)kt * 32 * NHD + n0;
            #pragma unroll
            for (int i = 0; i < 4; i++) {
                int id = tid + i * 256;
                int kr = id >> 5, co = (id & 31) << 2;
                int src = INV32(kr);
                cp16(bb + (kr * BNN_STR + co) * 4, bs + (size_t)src * NHD + co);
            }
        } else {
            const float* bs = Bsrc + (size_t)n0 * NHD + (size_t)kt * 32;
            #pragma unroll
            for (int i = 0; i < 4; i++) {
                int id = tid + i * 256;
                int nr = id >> 3, co = (id & 7) << 2;
                cp16(bb + (nr * AS_STR + co) * 4, bs + (size_t)nr * NHD + co);
            }
        }
        CP_COMMIT();
    };

    auto compute = [&](int st) {
        const uint32_t* Ab = Asm + st * AS_W + (wm * 64) * AS_STR;
        const uint32_t* Bb = Bsm + st * BW;
        #pragma unroll
        for (int kk = 0; kk < 4; kk++) {
            const int pc = kk * 8 + c4 * 2;   // permuted position of (kk*8+c4, +4)
            uint32_t af[4][4];
            #pragma unroll
            for (int i = 0; i < 4; i++) {
                int r = i * 16 + g;
                uint2 u0 = *(const uint2*)&Ab[r * AS_STR + pc];
                uint2 u1 = *(const uint2*)&Ab[(r + 8) * AS_STR + pc];
                af[i][0] = u0.x; af[i][1] = u1.x; af[i][2] = u0.y; af[i][3] = u1.y;
            }
            #pragma unroll
            for (int j = 0; j < 4; j++) {
                uint32_t bf[2];
                if (!NT) {
                    bf[0] = Bb[pc * BNN_STR + wn * 32 + j * 8 + g];
                    bf[1] = Bb[(pc + 1) * BNN_STR + wn * 32 + j * 8 + g];
                } else {
                    uint2 ub = *(const uint2*)&Bb[(wn * 32 + j * 8 + g) * AS_STR + pc];
                    bf[0] = ub.x; bf[1] = ub.y;
                }
                #pragma unroll
                for (int i = 0; i < 4; i++)
                    mma_tf32(acc[i][j], af[i], bf);
            }
        }
    };

    load_stage(0, 0);
    load_stage(1, 1);
    for (int kt = 0; kt < 64; kt++) {
        if (kt < 63) CP_WAIT(1); else CP_WAIT(0);
        __syncthreads();
        if (!NT) {
            if (kt + 2 < 64) load_stage((kt + 2) % 3, kt + 2);
            compute(kt % 3);
        } else {
            compute(kt & 1);
            if (kt + 2 < 64) {
                __syncthreads();          // all warps done reading this buffer
                load_stage(kt & 1, kt + 2);
            }
        }
    }

    if (!NT) {
        const int head = blockIdx.x;   // BN=128 == HD
        float* dst = (z == 0) ? g_q : (z == 1) ? g_k : g_v;
        #pragma unroll
        for (int i = 0; i < 4; i++) {
            int m = m0 + wm * 64 + i * 16 + g;
            int b = m >> 11, s = m & 2047;
            #pragma unroll
            for (int j = 0; j < 4; j++) {
                int h = wn * 32 + j * 8 + 2 * c4;
                size_t o = ((size_t)(b * NHN + head) * SS + s) * HD + h;
                *(float2*)&dst[o] = make_float2(__uint_as_float(f2tf(acc[i][j][0])),
                                                __uint_as_float(f2tf(acc[i][j][1])));
                *(float2*)&dst[o + 8 * HD] = make_float2(__uint_as_float(f2tf(acc[i][j][2])),
                                                         __uint_as_float(f2tf(acc[i][j][3])));
            }
        }
    } else {
        #pragma unroll
        for (int i = 0; i < 4; i++) {
            int m = m0 + wm * 64 + i * 16 + g;
            #pragma unroll
            for (int j = 0; j < 4; j++) {
                int col = n0 + wn * 32 + j * 8 + 2 * c4;
                *(float2*)&out[(size_t)m * DD + col] =
                    make_float2(acc[i][j][0], acc[i][j][1]);
                *(float2*)&out[(size_t)(m + 8) * DD + col] =
                    make_float2(acc[i][j][2], acc[i][j][3]);
            }
        }
    }
}

// =====================================================================
// tf32 tensor-core flash attention (prefill, causal).
// LPT grid: x = bn (32), y = reversed qt (16) -> the 148 heaviest CTAs
// form wave 1 and work-stealing descends by length.
// K prefetch + double-buffered V; P/V key-permuted, conflict-free strides.
// Epilogue writes g_attn k-permuted per 8-block (consumed by NT GEMM).
// =====================================================================
#define FA_BM 128
#define FA_BN 64
#define QS_STRIDE 132
#define KS_STRIDE 132
#define VS_STRIDE 140
#define PS_STRIDE 72
#define QS_SIZE (FA_BM*QS_STRIDE)
#define KS_SIZE (FA_BN*KS_STRIDE)
#define VS_W    (FA_BN*VS_STRIDE)
#define PS_SIZE (FA_BM*PS_STRIDE)
#define FA_SMEM_BYTES ((QS_SIZE+KS_SIZE+2*VS_W+PS_SIZE)*4)   // 209920

__global__ __launch_bounds__(256, 1) void flash_attn_tc() {
    extern __shared__ uint32_t smu[];
    uint32_t* Qs = smu;
    uint32_t* Ks = smu + QS_SIZE;
    uint32_t* Vs = Ks + KS_SIZE;            // two buffers of VS_W
    uint32_t* Ps = Vs + 2 * VS_W;
    const uint32_t s_q = (uint32_t)__cvta_generic_to_shared(smu);
    const uint32_t s_k = s_q + QS_SIZE * 4;
    const uint32_t s_v = s_k + KS_SIZE * 4;

    const int bn  = blockIdx.x;              // 0..31
    const int qt  = 15 - blockIdx.y;         // LPT: longest (qt=15) first
    const int tid = threadIdx.x;
    const int warp = tid >> 5, lane = tid & 31;
    const int g = lane >> 2, c4 = lane & 3;

    const float* qh = g_q + (size_t)bn * SS * HD;
    const float* kh = g_k + (size_t)bn * SS * HD;
    const float* vh = g_v + (size_t)bn * SS * HD;

    {
        const float* src = qh + (size_t)qt * FA_BM * HD;
        #pragma unroll
        for (int i = 0; i < 16; i++) {
            int id = tid + i * 256;
            int r = id >> 5, c = (id & 31) << 2;
            cp16(s_q + (r * QS_STRIDE + c) * 4, src + (size_t)r * HD + c);
        }
        CP_COMMIT();
    }
    {
        #pragma unroll
        for (int i = 0; i < 8; i++) {
            int id = tid + i * 256;
            int r = id >> 5, c = (id & 31) << 2;
            cp16(s_k + (r * KS_STRIDE + c) * 4, kh + (size_t)r * HD + c);
            cp16(s_v + (PERM8(r) * VS_STRIDE + c) * 4, vh + (size_t)r * HD + c);
        }
        CP_COMMIT();
    }

    float m_i[2] = {-INFINITY, -INFINITY};
    float l_i[2] = {0.f, 0.f};
    float oacc[16][4];
    #pragma unroll
    for (int nt = 0; nt < 16; nt++)
        #pragma unroll
        for (int e = 0; e < 4; e++) oacc[nt][e] = 0.f;

    const int nkt = 2 * qt + 2;
    const uint32_t* Qw = Qs + (warp * 16) * QS_STRIDE;
    const uint32_t* Pw = Ps + (warp * 16) * PS_STRIDE;
    int buf = 0;

    for (int kt = 0; kt < nkt; kt++) {
        CP_WAIT(0);
        __syncthreads();

        float sacc[8][4];
        #pragma unroll
        for (int nt = 0; nt < 8; nt++)
            #pragma unroll
            for (int e = 0; e < 4; e++) sacc[nt][e] = 0.f;

        #pragma unroll
        for (int kk = 0; kk < 16; kk++) {
            const int cb = kk * 8 + c4;
            uint32_t af[4];
            af[0] = Qw[g * QS_STRIDE + cb];
            af[1] = Qw[(g + 8) * QS_STRIDE + cb];
            af[2] = Qw[g * QS_STRIDE + cb + 4];
            af[3] = Qw[(g + 8) * QS_STRIDE + cb + 4];
            #pragma unroll
            for (int nt = 0; nt < 8; nt++) {
                uint32_t bf[2];
                bf[0] = Ks[(nt * 8 + g) * KS_STRIDE + cb];
                bf[1] = Ks[(nt * 8 + g) * KS_STRIDE + cb + 4];
                mma_tf32(sacc[nt], af, bf);
            }
        }
        __syncthreads();   // all warps done reading Ks

        if (kt + 1 < nkt) {
            const float* ks = kh + (size_t)(kt + 1) * FA_BN * HD;
            const float* vs = vh + (size_t)(kt + 1) * FA_BN * HD;
            const uint32_t vdst = s_v + (buf ^ 1) * VS_W * 4;
            #pragma unroll
            for (int i = 0; i < 8; i++) {
                int id = tid + i * 256;
                int r = id >> 5, c = (id & 31) << 2;
                cp16(s_k + (r * KS_STRIDE + c) * 4, ks + (size_t)r * HD + c);
                cp16(vdst + (PERM8(r) * VS_STRIDE + c) * 4, vs + (size_t)r * HD + c);
            }
            CP_COMMIT();
        }

        const bool domask = (kt >= 2 * qt);
        #pragma unroll
        for (int i = 0; i < 2; i++) {
            const int qrow = qt * 128 + warp * 16 + g + i * 8;
            float rm = -INFINITY;
            #pragma unroll
            for (int nt = 0; nt < 8; nt++) {
                #pragma unroll
                for (int e = 0; e < 2; e++) {
                    float v = sacc[nt][i * 2 + e] * ATT_SCALE;
                    if (domask && (kt * 64 + nt * 8 + 2 * c4 + e) > qrow) v = -INFINITY;
                    sacc[nt][i * 2 + e] = v;
                    rm = fmaxf(rm, v);
                }
            }
            rm = fmaxf(rm, __shfl_xor_sync(0xffffffffu, rm, 1));
            rm = fmaxf(rm, __shfl_xor_sync(0xffffffffu, rm, 2));
            float mn   = fmaxf(m_i[i], rm);
            float corr = __expf(m_i[i] - mn);
            float rs = 0.f;
            #pragma unroll
            for (int nt = 0; nt < 8; nt++) {
                #pragma unroll
                for (int e = 0; e < 2; e++) {
                    float p = __expf(sacc[nt][i * 2 + e] - mn);
                    rs += p;
                    int jj = 2 * c4 + e;                 // col within 8-block
                    int phys = nt * 8 + PERM8(jj);       // key-permuted store
                    Ps[(warp * 16 + g + i * 8) * PS_STRIDE + phys] = f2tf(p);
                }
            }
            rs += __shfl_xor_sync(0xffffffffu, rs, 1);
            rs += __shfl_xor_sync(0xffffffffu, rs, 2);
            l_i[i] = l_i[i] * corr + rs;
            m_i[i] = mn;
            #pragma unroll
            for (int nt = 0; nt < 16; nt++) {
                oacc[nt][i * 2]     *= corr;
                oacc[nt][i * 2 + 1] *= corr;
            }
        }
        __syncwarp();

        const uint32_t* Vb = Vs + buf * VS_W;
        #pragma unroll
        for (int kk = 0; kk < 8; kk++) {
            const int pc = kk * 8 + c4 * 2;   // permuted pos of keys (kk*8+c4, +4)
            uint32_t af[4];
            {
                uint2 u0 = *(const uint2*)&Pw[g * PS_STRIDE + pc];
                uint2 u1 = *(const uint2*)&Pw[(g + 8) * PS_STRIDE + pc];
                af[0] = u0.x; af[1] = u1.x; af[2] = u0.y; af[3] = u1.y;
            }
            #pragma unroll
            for (int nt = 0; nt < 16; nt++) {
                uint32_t bf[2];
                bf[0] = Vb[pc * VS_STRIDE + nt * 8 + g];
                bf[1] = Vb[(pc + 1) * VS_STRIDE + nt * 8 + g];
                mma_tf32(oacc[nt], af, bf);
            }
        }
        buf ^= 1;
    }

    // ---- finalize; write g_attn k-permuted per 8-block ----
    const int b = bn >> 4, n = bn & 15;
    #pragma unroll
    for (int i = 0; i < 2; i++) {
        float inv = 1.f / l_i[i];
        int row = qt * 128 + warp * 16 + g + i * 8;
        size_t base = ((size_t)b * SS + row) * NHD + (size_t)n * HD;
        #pragma unroll
        for (int nt = 0; nt < 16; nt++) {
            #pragma unroll
            for (int e = 0; e < 2; e++) {
                int col = nt * 8 + 2 * c4 + e;
                int phys = PERM8(col);
                g_attn[base + phys] =
                    __uint_as_float(f2tf(oacc[nt][i * 2 + e] * inv));
            }
        }
    }
}

// =====================================================================
// Decode path (untouched — reads only g_k/g_v/original weights)
// =====================================================================
__global__ void zero_decode() {
    int i = blockIdx.x * 256 + threadIdx.x;
    if (i < BB * NHD) { g_q1[i] = 0.f; g_k1[i] = 0.f; g_v1[i] = 0.f; }
}

__global__ void decode_proj2(const float* __restrict__ xn,
                             const float* __restrict__ wq,
                             const float* __restrict__ wk,
                             const float* __restrict__ wv) {
    int j  = blockIdx.x * 256 + threadIdx.x;
    int d0 = blockIdx.y * 128;
    float aq0=0,aq1=0,ak0=0,ak1=0,av0=0,av1=0;
    #pragma unroll 4
    for (int d = d0; d < d0 + 128; d++) {
        float x0 = xn[d], x1 = xn[DD + d];
        float q = wq[(size_t)d * NHD + j];
        float k = wk[(size_t)d * NHD + j];
        float v = wv[(size_t)d * NHD + j];
        aq0 += x0 * q; aq1 += x1 * q;
        ak0 += x0 * k; ak1 += x1 * k;
        av0 += x0 * v; av1 += x1 * v;
    }
    atomicAdd(&g_q1[j], aq0); atomicAdd(&g_q1[NHD + j], aq1);
    atomicAdd(&g_k1[j], ak0); atomicAdd(&g_k1[NHD + j], ak1);
    atomicAdd(&g_v1[j], av0); atomicAdd(&g_v1[NHD + j], av1);
}

__global__ void dec_attn_split() {
    __shared__ float qsm[HD];
    __shared__ float sc[257];
    __shared__ float red[256];
    const int bn = blockIdx.x, sp = blockIdx.y;
    const int b = bn >> 4, n = bn & 15;
    const int tid = threadIdx.x;
    const int nk = (sp == 7) ? 257 : 256;
    const int base = sp * 256;

    if (tid < HD) qsm[tid] = g_q1[b * NHD + n * HD + tid];
    __syncthreads();

    float lv = -INFINITY;
    for (int j = tid; j < nk; j += 256) {
        int key = base + j;
        const float* kp = (key < SS) ? &g_k[((size_t)bn * SS + key) * HD]
                                     : &g_k1[b * NHD + n * HD];
        float d = 0.f;
        #pragma unroll 8
        for (int h = 0; h < HD; h++) d += qsm[h] * kp[h];
        d *= ATT_SCALE;
        sc[j] = d;
        lv = fmaxf(lv, d);
    }
    red[tid] = lv; __syncthreads();
    for (int o = 128; o; o >>= 1) {
        if (tid < o) red[tid] = fmaxf(red[tid], red[tid + o]);
        __syncthreads();
    }
    const float m = red[0];
    __syncthreads();

    float ls = 0.f;
    for (int j = tid; j < nk; j += 256) {
        float p = __expf(sc[j] - m);
        sc[j] = p;
        ls += p;
    }
    red[tid] = ls; __syncthreads();
    for (int o = 128; o; o >>= 1) {
        if (tid < o) red[tid] += red[tid + o];
        __syncthreads();
    }
    const float l = red[0];
    __syncthreads();

    const int h = tid & 127, half = tid >> 7;
    const int j0 = half ? (nk / 2) : 0;
    const int j1 = half ? nk : (nk / 2);
    float o = 0.f;
    for (int j = j0; j < j1; j++) {
        int key = base + j;
        const float* vp = (key < SS) ? &g_v[((size_t)bn * SS + key) * HD]
                                     : &g_v1[b * NHD + n * HD];
        o += sc[j] * vp[h];
    }
    red[tid] = o; __syncthreads();
    if (tid < HD)
        g_do[(bn * 8 + sp) * HD + tid] = red[tid] + red[128 + tid];
    if (tid == 0) { g_dm[bn * 8 + sp] = m; g_dl[bn * 8 + sp] = l; }
}

__global__ void dec_attn_reduce() {
    const int bn = blockIdx.x, tid = threadIdx.x;
    const int b = bn >> 4, n = bn & 15;
    float m = -INFINITY;
    #pragma unroll
    for (int s = 0; s < 8; s++) m = fmaxf(m, g_dm[bn * 8 + s]);
    float l = 0.f, o = 0.f;
    #pragma unroll
    for (int s = 0; s < 8; s++) {
        float w = __expf(g_dm[bn * 8 + s] - m);
        l += g_dl[bn * 8 + s] * w;
        o += g_do[(bn * 8 + s) * HD + tid] * w;
    }
    g_attn1[b * NHD + n * HD + tid] = o / l;
}

__global__ void decode_outproj(const float* __restrict__ WO, float* __restrict__ out) {
    int gw   = (blockIdx.x * 256 + threadIdx.x) >> 5;
    int lane = threadIdx.x & 31;
    int b = gw >> 11, d = gw & 2047;
    const float* a = g_attn1 + (size_t)b * NHD;
    const float* w = WO + (size_t)d * NHD;
    float acc = 0.f;
    for (int k = lane; k < NHD; k += 32) acc += a[k] * w[k];
    #pragma unroll
    for (int o = 16; o; o >>= 1) acc += __shfl_xor_sync(0xffffffffu, acc, o);
    if (lane == 0) out[(size_t)b * DD + d] = acc;
}

// =====================================================================
// launch
// =====================================================================
extern "C" void kernel_launch(void* const* d_in, const int* in_sizes, int n_in,
                              void* d_out, int out_size) {
    const float* x   = (const float*)d_in[0];
    const float* xn  = (const float*)d_in[1];
    const float* wq  = (const float*)d_in[2];
    const float* wk  = (const float*)d_in[3];
    const float* wv  = (const float*)d_in[4];
    const float* wo  = (const float*)d_in[5];
    float* out = (float*)d_out;

    cudaFuncSetAttribute((const void*)flash_attn_tc,
                         cudaFuncAttributeMaxDynamicSharedMemorySize, FA_SMEM_BYTES);
    cudaFuncSetAttribute((const void*)mma_gemm<0>,
                         cudaFuncAttributeMaxDynamicSharedMemorySize, GEMM_SMEM_NN);
    cudaFuncSetAttribute((const void*)mma_gemm<1>,
                         cudaFuncAttributeMaxDynamicSharedMemorySize, GEMM_SMEM_NT);

    zero_decode<<<16, 256>>>();
    preround<<<dim3(8192, 5), 256>>>(x, wq, wk, wv, wo);
    decode_proj2<<<dim3(8, 16), 256>>>(xn, wq, wk, wv);

    mma_gemm<0><<<dim3(16, 32, 3), 256, GEMM_SMEM_NN>>>(nullptr);  // fused QKV

    flash_attn_tc<<<dim3(32, 16), 256, FA_SMEM_BYTES>>>();         // LPT grid

    mma_gemm<1><<<dim3(16, 32, 1), 256, GEMM_SMEM_NT>>>(out);      // out-proj

    dec_attn_split<<<dim3(32, 8), 256>>>();
    dec_attn_reduce<<<32, 128>>>();
    decode_outproj<<<512, 256>>>(wo, out + PREFILL_ELEMS);
}